// round 15
// baseline (speedup 1.0000x reference)
#include <cuda_runtime.h>
#include <cuda_bf16.h>
#include <cstdint>
#include <cstddef>

#define NNODES 50000
#define NEDGES 500000
#define HDIM   128
#define EBLOCKS ((NEDGES + 127) / 128)
#define NBLOCKS ((NNODES + 127) / 128)

typedef unsigned long long ull;

// ---------------- device scratch ----------------
__device__ float g_x[2][(size_t)NNODES * HDIM];
__device__ float g_pos[2][(size_t)NNODES * 3];
__device__ float g_intra[(size_t)NNODES * HDIM];   // hsum = sum_e h_e per dst
__device__ float g_pdelta[(size_t)NNODES * 3];
__device__ float g_hidden[(size_t)NNODES * 256];
__device__ float g_P[(size_t)NNODES * HDIM];
__device__ float g_Q[(size_t)NNODES * HDIM];
__device__ float g_C1[3][128 * 256];   // W2 @ aW1
__device__ float g_C2[3][128 * 256];   // W2 @ nW1[128:]
__device__ float g_c1b[3][256];        // b2 @ aW1 + ab1
__device__ float g_c2b[3][256];        // b2 @ nW1[128:]
__device__ int   g_deg[NNODES];
__device__ int   g_idx64;

__device__ __forceinline__ void red_add_v2(float* a, float x, float y) {
    asm volatile("red.global.add.v2.f32 [%0], {%1,%2};" :: "l"(a), "f"(x), "f"(y) : "memory");
}
__device__ __forceinline__ void red_add_v4(float* a, float x, float y, float z, float w) {
    asm volatile("red.global.add.v4.f32 [%0], {%1,%2,%3,%4};"
                 :: "l"(a), "f"(x), "f"(y), "f"(z), "f"(w) : "memory");
}
__device__ __forceinline__ void red_add_f32(float* a, float v) {
    asm volatile("red.global.add.f32 [%0], %1;" :: "l"(a), "f"(v) : "memory");
}
__device__ __forceinline__ uint32_t smem_to_u32(const void* p) {
    uint32_t a;
    asm("{ .reg .u64 t; cvta.to.shared.u64 t, %1; cvt.u32.u64 %0, t; }" : "=r"(a) : "l"(p));
    return a;
}

// ---------------- packed fp32x2 (node-side SIMT GEMMs) ----------------
__device__ __forceinline__ ull pk2(float lo, float hi) {
    ull r; asm("mov.b64 %0, {%1, %2};" : "=l"(r) : "f"(lo), "f"(hi)); return r;
}
__device__ __forceinline__ void upk2(float& lo, float& hi, ull v) {
    asm("mov.b64 {%0, %1}, %2;" : "=f"(lo), "=f"(hi) : "l"(v));
}
__device__ __forceinline__ void fmax2(ull& c, ull a, ull b) {
    asm("fma.rn.f32x2 %0, %1, %2, %0;" : "+l"(c) : "l"(a), "l"(b));
}

// ---------------- mma.sync helpers (base PTX, validated R9) ----------
__device__ __forceinline__ void ldsm_x4(uint32_t addr, uint32_t* r) {
    asm volatile("ldmatrix.sync.aligned.m8n8.x4.shared.b16 {%0,%1,%2,%3}, [%4];"
                 : "=r"(r[0]), "=r"(r[1]), "=r"(r[2]), "=r"(r[3]) : "r"(addr));
}
__device__ __forceinline__ void mma_bf16(float* c, const uint32_t* a, const uint32_t* b) {
    asm volatile("mma.sync.aligned.m16n8k16.row.col.f32.bf16.bf16.f32 "
                 "{%0,%1,%2,%3}, {%4,%5,%6,%7}, {%8,%9}, {%0,%1,%2,%3};"
                 : "+f"(c[0]), "+f"(c[1]), "+f"(c[2]), "+f"(c[3])
                 : "r"(a[0]), "r"(a[1]), "r"(a[2]), "r"(a[3]), "r"(b[0]), "r"(b[1]));
}

// SW128-swizzled byte offset in a 128x128 bf16 tile (validated R9)
__device__ __forceinline__ uint32_t sw_off(int r, int c) {
    uint32_t b = ((uint32_t)(c >> 6) << 14) + ((uint32_t)(r >> 3) << 10) +
                 ((uint32_t)(r & 7) << 7) + ((uint32_t)(c & 63) << 1);
    return b ^ ((b >> 3) & 0x70);
}
__device__ __forceinline__ void bsplit(float a, unsigned short& h, unsigned short& l) {
    __nv_bfloat16 bh = __float2bfloat16_rn(a);
    float rest = a - __bfloat162float(bh);
    __nv_bfloat16 bl = __float2bfloat16_rn(rest);
    h = __bfloat16_as_ushort(bh); l = __bfloat16_as_ushort(bl);
}
__device__ __forceinline__ void store_pair(char* hi, char* lo, int r, int c, float v0, float v1) {
    unsigned short h0, l0, h1, l1;
    bsplit(v0, h0, l0); bsplit(v1, h1, l1);
    uint32_t off = sw_off(r, c);
    *(uint32_t*)(hi + off) = (uint32_t)h0 | ((uint32_t)h1 << 16);
    *(uint32_t*)(lo + off) = (uint32_t)l0 | ((uint32_t)l1 << 16);
}
// stage W^T split: tile[n][k] = W[k][nbase+n]
__device__ __forceinline__ void stage_wT(char* hi, char* lo, const float* __restrict__ W,
                                         int stride, int nbase, int start, int step) {
    for (int idx = start; idx < 128 * 32; idx += step) {
        int k = idx >> 5, n0 = (idx & 31) * 4;
        float4 v = *reinterpret_cast<const float4*>(W + (size_t)k * stride + nbase + n0);
        float vv[4] = {v.x, v.y, v.z, v.w};
#pragma unroll
        for (int j = 0; j < 4; j++) {
            unsigned short hh, ll;
            bsplit(vv[j], hh, ll);
            uint32_t off = sw_off(n0 + j, k);
            *(unsigned short*)(hi + off) = hh;
            *(unsigned short*)(lo + off) = ll;
        }
    }
}

// warp 16x128 slice of 128x128x128 GEMM, 3-term split, TERM-MAJOR mma order
// (breaks the same-accumulator RAW chains that throttled R9), B via x4 loads.
__device__ __forceinline__ void warp_mma3(
    float (*acc)[4], uint32_t a_hi, uint32_t a_lo, uint32_t w_hi, uint32_t w_lo,
    int row0, int lane)
{
    const int arow  = row0 + (lane & 15);
    const int acolh = (lane >> 4) * 8;
    const int btile = lane >> 3;          // 0..3
    const int brow  = lane & 7;
    const int bnt   = (btile >> 1) * 8;   // odd-nt row offset within pair
    const int bkh   = (btile & 1) * 8;    // k-half
    for (int k0 = 0; k0 < 8; k0++) {
        uint32_t ah[4], al[4];
        uint32_t aoff = sw_off(arow, k0 * 16 + acolh);
        ldsm_x4(a_hi + aoff, ah);
        ldsm_x4(a_lo + aoff, al);
        uint32_t bh[32], bl[32];
#pragma unroll
        for (int p = 0; p < 8; p++) {
            uint32_t boff = sw_off(p * 16 + bnt + brow, k0 * 16 + bkh);
            ldsm_x4(w_hi + boff, &bh[p * 4]);
            ldsm_x4(w_lo + boff, &bl[p * 4]);
        }
#pragma unroll
        for (int nt = 0; nt < 16; nt++) mma_bf16(acc[nt], ah, &bh[nt * 2]);
#pragma unroll
        for (int nt = 0; nt < 16; nt++) mma_bf16(acc[nt], ah, &bl[nt * 2]);
#pragma unroll
        for (int nt = 0; nt < 16; nt++) mma_bf16(acc[nt], al, &bh[nt * 2]);
    }
}

// ---------------- SIMT GEMM helpers (node-side) ----------------
__device__ __forceinline__ void load_w128(float* Ws, const float* __restrict__ src, int row_stride)
{
    for (int idx = threadIdx.x; idx < 128 * 32; idx += 256) {
        int r = idx >> 5, c4 = idx & 31;
        reinterpret_cast<float4*>(Ws + r * 128)[c4] =
            reinterpret_cast<const float4*>(src + (size_t)r * row_stride)[c4];
    }
}
__device__ __forceinline__ void mm128p(const float* __restrict__ As, const float* __restrict__ Ws,
                                       int rb, int c0, ull (*acc)[4])
{
#pragma unroll 4
    for (int k = 0; k < 128; k++) {
        ull av[8];
#pragma unroll
        for (int i = 0; i < 8; i++) { float a = As[(rb + i) * 129 + k]; av[i] = pk2(a, a); }
        const ull* w0 = reinterpret_cast<const ull*>(Ws + k * 128 + c0);
        const ull* w1 = reinterpret_cast<const ull*>(Ws + k * 128 + c0 + 64);
        const ull b0 = w0[0], b1 = w0[1], b2 = w1[0], b3 = w1[1];
#pragma unroll
        for (int i = 0; i < 8; i++) {
            fmax2(acc[i][0], av[i], b0);
            fmax2(acc[i][1], av[i], b1);
            fmax2(acc[i][2], av[i], b2);
            fmax2(acc[i][3], av[i], b3);
        }
    }
}

// smem layouts
#define OFF_IDX  0
#define OFF_A_HI 1024
#define OFF_A_LO (OFF_A_HI + 32768)
#define OFF_W_HI (OFF_A_LO + 32768)
#define OFF_W_LO (OFF_W_HI + 32768)
#define EDGE_SMEM (OFF_W_LO + 32768)
#define NODE_SMEM ((128 * 129 + 128 * 128) * 4)

#define DECL_SMEM_RAW extern __shared__ __align__(1024) char sm_raw[]

// ---------------- prep / deg ----------------
__global__ void prep_kernel(const float* __restrict__ x, const float* __restrict__ pos,
                            const void* __restrict__ ei)
{
    const long long stride = (long long)gridDim.x * blockDim.x;
    const long long t0 = (long long)blockIdx.x * blockDim.x + threadIdx.x;
    float4* xb = reinterpret_cast<float4*>(g_x[0]);
    const float4* xs = reinterpret_cast<const float4*>(x);
    float4* ib = reinterpret_cast<float4*>(g_intra);
    const float4 z4 = make_float4(0.f, 0.f, 0.f, 0.f);
    const long long nx4 = (long long)NNODES * (HDIM / 4);
    for (long long t = t0; t < nx4; t += stride) { xb[t] = xs[t]; ib[t] = z4; }
    for (long long t = t0; t < (long long)NNODES * 3; t += stride) {
        g_pos[0][t] = pos[t]; g_pdelta[t] = 0.f;
    }
    for (long long t = t0; t < NNODES; t += stride) g_deg[t] = 0;
    if (t0 == 0) {
        const unsigned* u = (const unsigned*)ei;
        int is64 = 1;
        for (int k = 0; k < 128; k++) if (u[2 * k + 1] != 0u) { is64 = 0; break; }
        g_idx64 = is64;
    }
}

__global__ void deg_kernel(const void* __restrict__ ei)
{
    int e = blockIdx.x * blockDim.x + threadIdx.x;
    if (e >= NEDGES) return;
    int d;
    if (g_idx64) d = (int)((const long long*)ei)[(size_t)NEDGES + e];
    else         d = ((const int*)ei)[NEDGES + e];
    atomicAdd(&g_deg[d], 1);
}

// ---------------- fold kernels ----------------
__global__ void __launch_bounds__(256) fold_mat_kernel(
    const float* __restrict__ mW2, const float* __restrict__ aW1,
    const float* __restrict__ nW1)
{
    DECL_SMEM_RAW;
    float* smf = reinterpret_cast<float*>(sm_raw);
    float* As = smf;
    float* Ws = smf + 128 * 129;

    const int tid  = threadIdx.x;
    const int rb   = (tid >> 4) * 8;
    const int c0   = (tid & 15) * 4;
    const int half = blockIdx.x;
    const int l    = blockIdx.y;
    const int tgt  = blockIdx.z;

    const float* A = mW2 + (size_t)l * 128 * 128;
    const float* W = tgt == 0 ? (aW1 + (size_t)l * 128 * 256 + half * 128)
                              : (nW1 + (size_t)l * 256 * 256 + (size_t)128 * 256 + half * 128);
    float* out = (tgt == 0 ? g_C1[l] : g_C2[l]) + half * 128;

    for (int idx = tid; idx < 128 * 32; idx += 256) {
        int r = idx >> 5, c4 = idx & 31;
        float4 v = reinterpret_cast<const float4*>(A + (size_t)r * 128)[c4];
        float* a = As + r * 129 + c4 * 4;
        a[0] = v.x; a[1] = v.y; a[2] = v.z; a[3] = v.w;
    }
    load_w128(Ws, W, 256);
    __syncthreads();

    ull acc[8][4];
#pragma unroll
    for (int i = 0; i < 8; i++)
#pragma unroll
        for (int j = 0; j < 4; j++) acc[i][j] = 0ull;
    mm128p(As, Ws, rb, c0, acc);

#pragma unroll
    for (int i = 0; i < 8; i++) {
        float* orow = out + (size_t)(rb + i) * 256;
        float v0, v1;
        upk2(v0, v1, acc[i][0]); orow[c0] = v0;      orow[c0 + 1] = v1;
        upk2(v0, v1, acc[i][1]); orow[c0 + 2] = v0;  orow[c0 + 3] = v1;
        upk2(v0, v1, acc[i][2]); orow[c0 + 64] = v0; orow[c0 + 65] = v1;
        upk2(v0, v1, acc[i][3]); orow[c0 + 66] = v0; orow[c0 + 67] = v1;
    }
}

__global__ void fold_bias_kernel(
    const float* __restrict__ mb2, const float* __restrict__ aW1,
    const float* __restrict__ ab1, const float* __restrict__ nW1)
{
    const int c = threadIdx.x;
    const int l = blockIdx.x;
    const float* b2 = mb2 + (size_t)l * 128;
    float s1 = 0.f, s2 = 0.f;
    const float* A1 = aW1 + (size_t)l * 128 * 256;
    const float* A2 = nW1 + (size_t)l * 256 * 256 + (size_t)128 * 256;
    for (int j = 0; j < 128; j++) {
        float b = b2[j];
        s1 += b * A1[(size_t)j * 256 + c];
        s2 += b * A2[(size_t)j * 256 + c];
    }
    g_c1b[l][c] = s1 + ab1[(size_t)l * 256 + c];
    g_c2b[l][c] = s2;
}

// ---------------- pq kernel ----------------
__global__ void __launch_bounds__(256) pq_kernel(int cur, const float* __restrict__ mW1)
{
    DECL_SMEM_RAW;
    float* smf = reinterpret_cast<float*>(sm_raw);
    float* As = smf;
    float* Ws = smf + 128 * 129;

    const float* __restrict__ x = g_x[cur];
    const int tid = threadIdx.x;
    const int rb  = (tid >> 4) * 8;
    const int c0  = (tid & 15) * 4;
    const int n0  = blockIdx.x * 128;
    const int half = blockIdx.y;

    for (int idx = tid; idx < 128 * 32; idx += 256) {
        int r = idx >> 5, c4 = idx & 31;
        int n = n0 + r; if (n > NNODES - 1) n = NNODES - 1;
        float4 v = reinterpret_cast<const float4*>(x + (size_t)n * HDIM)[c4];
        float* a = As + r * 129 + c4 * 4;
        a[0] = v.x; a[1] = v.y; a[2] = v.z; a[3] = v.w;
    }
    load_w128(Ws, mW1 + (size_t)half * 128 * HDIM, HDIM);
    __syncthreads();

    ull acc[8][4];
#pragma unroll
    for (int i = 0; i < 8; i++)
#pragma unroll
        for (int j = 0; j < 4; j++) acc[i][j] = 0ull;
    mm128p(As, Ws, rb, c0, acc);

    float* __restrict__ out = half ? g_Q : g_P;
#pragma unroll
    for (int i = 0; i < 8; i++) {
        int n = n0 + rb + i;
        if (n >= NNODES) break;
        float* orow = out + (size_t)n * HDIM;
        float v0, v1;
        upk2(v0, v1, acc[i][0]); orow[c0] = v0;     orow[c0 + 1] = v1;
        upk2(v0, v1, acc[i][1]); orow[c0 + 2] = v0; orow[c0 + 3] = v1;
        upk2(v0, v1, acc[i][2]); orow[c0 + 64] = v0; orow[c0 + 65] = v1;
        upk2(v0, v1, acc[i][3]); orow[c0 + 66] = v0; orow[c0 + 67] = v1;
    }
}

// ---------------- mma edge kernel: 3 phases ----------------
__global__ void __launch_bounds__(256) edge_kernel_mma(
    int cur, int layer, const void* __restrict__ ei, const float* __restrict__ eattr,
    const float* __restrict__ mW1, const float* __restrict__ mb1,
    const float* __restrict__ aW2, const float* __restrict__ ab2)
{
    DECL_SMEM_RAW;
    char* sm = sm_raw;
    char* A_hi = sm + OFF_A_HI;
    char* A_lo = sm + OFF_A_LO;
    char* W_hi = sm + OFF_W_HI;
    char* W_lo = sm + OFF_W_LO;
    int* sdst = (int*)(sm + OFF_IDX);
    int* ssrc = sdst + 128;

    const uint32_t a_hi_u = smem_to_u32(A_hi);
    const uint32_t a_lo_u = smem_to_u32(A_lo);
    const uint32_t w_hi_u = smem_to_u32(W_hi);
    const uint32_t w_lo_u = smem_to_u32(W_lo);

    const float* __restrict__ C1  = g_C1[layer];
    const float* __restrict__ c1b = g_c1b[layer];
    const float* __restrict__ pos = g_pos[cur];

    const int tid  = threadIdx.x;
    const int lane = tid & 31;
    const int wid  = tid >> 5;
    const int row0 = wid * 16;
    const int e0   = blockIdx.x * 128;

    if (tid < 128) {
        int e = e0 + tid; if (e > NEDGES - 1) e = NEDGES - 1;
        int s, d;
        if (g_idx64) { const long long* p = (const long long*)ei;
                       s = (int)p[e]; d = (int)p[(size_t)NEDGES + e]; }
        else         { const int* p = (const int*)ei; s = p[e]; d = p[NEDGES + e]; }
        ssrc[tid] = s; sdst[tid] = d;
    }
    // stage A = eattr (split), W = W1c^T (split)
    for (int idx = tid; idx < 128 * 32; idx += 256) {
        int r = idx >> 5, c = (idx & 31) * 4;
        int e = e0 + r; if (e > NEDGES - 1) e = NEDGES - 1;
        float4 v = *reinterpret_cast<const float4*>(eattr + (size_t)e * HDIM + c);
        store_pair(A_hi, A_lo, r, c, v.x, v.y);
        store_pair(A_hi, A_lo, r, c + 2, v.z, v.w);
    }
    stage_wT(W_hi, W_lo, mW1 + (size_t)2 * 128 * HDIM, 128, 0, tid, 256);
    __syncthreads();

    const int lr0 = row0 + (lane >> 2);
    const int lr1 = lr0 + 8;
    const int cb  = 2 * (lane & 3);
    const bool live0 = (e0 + lr0) < NEDGES;
    const bool live1 = (e0 + lr1) < NEDGES;

    float acc[16][4];

    // ---- phase 1: h = relu(Eattr@W1c + b1 + P[dst] + Q[src])
#pragma unroll
    for (int nt = 0; nt < 16; nt++) {
        float2 b = *reinterpret_cast<const float2*>(mb1 + nt * 8 + cb);
        acc[nt][0] = b.x; acc[nt][1] = b.y; acc[nt][2] = b.x; acc[nt][3] = b.y;
    }
    warp_mma3(acc, a_hi_u, a_lo_u, w_hi_u, w_lo_u, row0, lane);
    __syncthreads();
    {
        const float* P0 = g_P + (size_t)sdst[lr0] * HDIM;
        const float* Q0 = g_Q + (size_t)ssrc[lr0] * HDIM;
        const float* P1 = g_P + (size_t)sdst[lr1] * HDIM;
        const float* Q1 = g_Q + (size_t)ssrc[lr1] * HDIM;
        float* i0 = g_intra + (size_t)sdst[lr0] * HDIM;
        float* i1 = g_intra + (size_t)sdst[lr1] * HDIM;
#pragma unroll
        for (int nt = 0; nt < 16; nt++) {
            int c = nt * 8 + cb;
            float2 p0 = *reinterpret_cast<const float2*>(P0 + c);
            float2 q0 = *reinterpret_cast<const float2*>(Q0 + c);
            float2 p1 = *reinterpret_cast<const float2*>(P1 + c);
            float2 q1 = *reinterpret_cast<const float2*>(Q1 + c);
            float h00 = fmaxf(acc[nt][0] + p0.x + q0.x, 0.f);
            float h01 = fmaxf(acc[nt][1] + p0.y + q0.y, 0.f);
            float h10 = fmaxf(acc[nt][2] + p1.x + q1.x, 0.f);
            float h11 = fmaxf(acc[nt][3] + p1.y + q1.y, 0.f);
            store_pair(A_hi, A_lo, lr0, c, h00, h01);
            store_pair(A_hi, A_lo, lr1, c, h10, h11);
            if (live0) red_add_v2(i0 + c, h00, h01);
            if (live1) red_add_v2(i1 + c, h10, h11);
        }
    }
    stage_wT(W_hi, W_lo, C1, 256, 0, tid, 256);
    __syncthreads();

    // ---- phases 2+3: folded acc MLP halves
    float wacc0 = 0.f, wacc1 = 0.f;
    for (int hp = 0; hp < 2; hp++) {
#pragma unroll
        for (int nt = 0; nt < 16; nt++) {
            float2 b = *reinterpret_cast<const float2*>(c1b + hp * 128 + nt * 8 + cb);
            acc[nt][0] = b.x; acc[nt][1] = b.y; acc[nt][2] = b.x; acc[nt][3] = b.y;
        }
        warp_mma3(acc, a_hi_u, a_lo_u, w_hi_u, w_lo_u, row0, lane);
#pragma unroll
        for (int nt = 0; nt < 16; nt++) {
            int c = hp * 128 + nt * 8 + cb;
            float2 wv = *reinterpret_cast<const float2*>(aW2 + c);
            wacc0 += fmaxf(acc[nt][0], 0.f) * wv.x + fmaxf(acc[nt][1], 0.f) * wv.y;
            wacc1 += fmaxf(acc[nt][2], 0.f) * wv.x + fmaxf(acc[nt][3], 0.f) * wv.y;
        }
        if (hp == 0) {
            __syncthreads();
            stage_wT(W_hi, W_lo, C1, 256, 128, tid, 256);
            __syncthreads();
        }
    }
    // reduce across quad lanes (same rows)
    wacc0 += __shfl_xor_sync(0xffffffffu, wacc0, 1);
    wacc0 += __shfl_xor_sync(0xffffffffu, wacc0, 2);
    wacc1 += __shfl_xor_sync(0xffffffffu, wacc1, 1);
    wacc1 += __shfl_xor_sync(0xffffffffu, wacc1, 2);

    if ((lane & 3) == 0) {
        const float b2 = __ldg(ab2);
        int rr[2] = {lr0, lr1};
        float wa[2] = {wacc0, wacc1};
#pragma unroll
        for (int i = 0; i < 2; i++) {
            int r = rr[i];
            if (e0 + r >= NEDGES) continue;
            int s = ssrc[r], d = sdst[r];
            float rx = pos[(size_t)s * 3 + 0] - pos[(size_t)d * 3 + 0];
            float ry = pos[(size_t)s * 3 + 1] - pos[(size_t)d * 3 + 1];
            float rz = pos[(size_t)s * 3 + 2] - pos[(size_t)d * 3 + 2];
            float inv = rsqrtf(rx * rx + ry * ry + rz * rz);
            float w = (wa[i] + b2) * inv;
            float* pb = g_pdelta + (size_t)d * 3;
            red_add_f32(pb + 0, w * rx);
            red_add_f32(pb + 1, w * ry);
            red_add_f32(pb + 2, w * rz);
        }
    }
}

// ---------------- node hidden ----------------
__global__ void __launch_bounds__(256) node_hidden_kernel(
    int cur, int layer, const float* __restrict__ nW1a, const float* __restrict__ nb1)
{
    DECL_SMEM_RAW;
    float* smf = reinterpret_cast<float*>(sm_raw);
    float* As = smf;
    float* Ws = smf + 128 * 129;

    const float* __restrict__ C2  = g_C2[layer];
    const float* __restrict__ c2b = g_c2b[layer];

    const float* __restrict__ x = g_x[cur];
    const int tid = threadIdx.x;
    const int rb  = (tid >> 4) * 8;
    const int c0  = (tid & 15) * 4;
    const int n0  = blockIdx.x * 128;
    const int hp  = blockIdx.y;

    ull acc[8][4];
#pragma unroll
    for (int i = 0; i < 8; i++) {
        const float* bb = nb1 + hp * 128;
        acc[i][0] = pk2(bb[c0], bb[c0 + 1]);
        acc[i][1] = pk2(bb[c0 + 2], bb[c0 + 3]);
        acc[i][2] = pk2(bb[c0 + 64], bb[c0 + 65]);
        acc[i][3] = pk2(bb[c0 + 66], bb[c0 + 67]);
    }

    for (int kc = 0; kc < 2; kc++) {
        for (int idx = tid; idx < 128 * 32; idx += 256) {
            int r = idx >> 5, c4 = idx & 31;
            int n = n0 + r; if (n > NNODES - 1) n = NNODES - 1;
            float4 v;
            if (kc == 0) v = reinterpret_cast<const float4*>(x + (size_t)n * HDIM)[c4];
            else {
                v = reinterpret_cast<const float4*>(g_intra + (size_t)n * HDIM)[c4];
                float dn = 1.f / fmaxf((float)g_deg[n], 1.f);
                v.x *= dn; v.y *= dn; v.z *= dn; v.w *= dn;
            }
            float* a = As + r * 129 + c4 * 4;
            a[0] = v.x; a[1] = v.y; a[2] = v.z; a[3] = v.w;
        }
        if (kc == 0) load_w128(Ws, nW1a + hp * 128, 256);
        else         load_w128(Ws, C2 + hp * 128, 256);
        __syncthreads();
        mm128p(As, Ws, rb, c0, acc);
        __syncthreads();
    }

#pragma unroll
    for (int i = 0; i < 8; i++) {
        int n = n0 + rb + i;
        if (n >= NNODES) break;
        float kap = g_deg[n] > 0 ? 1.f : 0.f;
        const float* cb = c2b + hp * 128;
        float* hrow = g_hidden + (size_t)n * 256 + hp * 128;
        float v0, v1;
        upk2(v0, v1, acc[i][0]);
        hrow[c0] = fmaxf(v0 + kap * cb[c0], 0.f);         hrow[c0 + 1] = fmaxf(v1 + kap * cb[c0 + 1], 0.f);
        upk2(v0, v1, acc[i][1]);
        hrow[c0 + 2] = fmaxf(v0 + kap * cb[c0 + 2], 0.f); hrow[c0 + 3] = fmaxf(v1 + kap * cb[c0 + 3], 0.f);
        upk2(v0, v1, acc[i][2]);
        hrow[c0 + 64] = fmaxf(v0 + kap * cb[c0 + 64], 0.f); hrow[c0 + 65] = fmaxf(v1 + kap * cb[c0 + 65], 0.f);
        upk2(v0, v1, acc[i][3]);
        hrow[c0 + 66] = fmaxf(v0 + kap * cb[c0 + 66], 0.f); hrow[c0 + 67] = fmaxf(v1 + kap * cb[c0 + 67], 0.f);
    }
}

// ---------------- node out ----------------
__global__ void __launch_bounds__(256) node_out_kernel(
    int cur, int nxt, const float* __restrict__ nW2, const float* __restrict__ nb2,
    float* __restrict__ pout)
{
    DECL_SMEM_RAW;
    float* smf = reinterpret_cast<float*>(sm_raw);
    float* As = smf;
    float* Ws = smf + 128 * 129;

    const int tid = threadIdx.x;
    const int rb  = (tid >> 4) * 8;
    const int c0  = (tid & 15) * 4;
    const int n0  = blockIdx.x * 128;

    ull acc[8][4];
#pragma unroll
    for (int i = 0; i < 8; i++) {
        acc[i][0] = pk2(nb2[c0], nb2[c0 + 1]);
        acc[i][1] = pk2(nb2[c0 + 2], nb2[c0 + 3]);
        acc[i][2] = pk2(nb2[c0 + 64], nb2[c0 + 65]);
        acc[i][3] = pk2(nb2[c0 + 66], nb2[c0 + 67]);
    }

    for (int kc = 0; kc < 2; kc++) {
        for (int idx = tid; idx < 128 * 32; idx += 256) {
            int r = idx >> 5, c4 = idx & 31;
            int n = n0 + r; if (n > NNODES - 1) n = NNODES - 1;
            float4 v = reinterpret_cast<const float4*>(g_hidden + (size_t)n * 256 + kc * 128)[c4];
            float* a = As + r * 129 + c4 * 4;
            a[0] = v.x; a[1] = v.y; a[2] = v.z; a[3] = v.w;
        }
        load_w128(Ws, nW2 + (size_t)kc * 128 * 128, 128);
        __syncthreads();
        mm128p(As, Ws, rb, c0, acc);
        __syncthreads();
    }

    float* __restrict__ xo = g_x[nxt];
#pragma unroll
    for (int i = 0; i < 8; i++) {
        int n = n0 + rb + i;
        if (n >= NNODES) break;
        float* xrow = xo + (size_t)n * HDIM;
        float v0, v1;
        upk2(v0, v1, acc[i][0]); xrow[c0] = v0;     xrow[c0 + 1] = v1;
        upk2(v0, v1, acc[i][1]); xrow[c0 + 2] = v0; xrow[c0 + 3] = v1;
        upk2(v0, v1, acc[i][2]); xrow[c0 + 64] = v0; xrow[c0 + 65] = v1;
        upk2(v0, v1, acc[i][3]); xrow[c0 + 66] = v0; xrow[c0 + 67] = v1;
    }

    for (int idx = tid; idx < 128 * 3; idx += 256) {
        int r = idx / 3, c = idx % 3;
        int n = n0 + r;
        if (n < NNODES) {
            float dn = 1.f / fmaxf((float)g_deg[n], 1.f);
            float p = g_pos[cur][(size_t)n * 3 + c] + g_pdelta[(size_t)n * 3 + c] * dn;
            g_pos[nxt][(size_t)n * 3 + c] = p;
            if (pout) pout[(size_t)n * 3 + c] = p;
            g_pdelta[(size_t)n * 3 + c] = 0.f;
        }
    }
    const float4 z4 = make_float4(0.f, 0.f, 0.f, 0.f);
    for (int idx = tid; idx < 128 * 32; idx += 256) {
        int r = idx >> 5, c4 = idx & 31;
        int n = n0 + r;
        if (n < NNODES)
            reinterpret_cast<float4*>(g_intra + (size_t)n * HDIM)[c4] = z4;
    }
}

extern "C" void kernel_launch(void* const* d_in, const int* in_sizes, int n_in,
                              void* d_out, int out_size)
{
    const float* x     = (const float*)d_in[0];
    const void*  ei    = d_in[1];
    const float* eattr = (const float*)d_in[2];
    const float* pos   = (const float*)d_in[3];
    const float* mW1 = (const float*)d_in[4];
    const float* mb1 = (const float*)d_in[5];
    const float* mW2 = (const float*)d_in[6];
    const float* mb2 = (const float*)d_in[7];
    const float* aW1 = (const float*)d_in[8];
    const float* ab1 = (const float*)d_in[9];
    const float* aW2 = (const float*)d_in[10];
    const float* ab2 = (const float*)d_in[11];
    const float* nW1 = (const float*)d_in[12];
    const float* nb1 = (const float*)d_in[13];
    const float* nW2 = (const float*)d_in[14];
    const float* nb2 = (const float*)d_in[15];

    cudaFuncSetAttribute(edge_kernel_mma, cudaFuncAttributeMaxDynamicSharedMemorySize, EDGE_SMEM);
    cudaFuncSetAttribute(pq_kernel, cudaFuncAttributeMaxDynamicSharedMemorySize, NODE_SMEM);
    cudaFuncSetAttribute(fold_mat_kernel, cudaFuncAttributeMaxDynamicSharedMemorySize, NODE_SMEM);
    cudaFuncSetAttribute(node_hidden_kernel, cudaFuncAttributeMaxDynamicSharedMemorySize, NODE_SMEM);
    cudaFuncSetAttribute(node_out_kernel, cudaFuncAttributeMaxDynamicSharedMemorySize, NODE_SMEM);

    prep_kernel<<<1024, 256>>>(x, pos, ei);
    deg_kernel<<<(NEDGES + 255) / 256, 256>>>(ei);
    fold_mat_kernel<<<dim3(2, 3, 2), 256, NODE_SMEM>>>(mW2, aW1, nW1);
    fold_bias_kernel<<<3, 256>>>(mb2, aW1, ab1, nW1);

    for (int l = 0; l < 3; l++) {
        int cur = l & 1, nxt = cur ^ 1;
        pq_kernel<<<dim3(NBLOCKS, 2), 256, NODE_SMEM>>>(cur, mW1 + (size_t)l * 384 * 128);
        edge_kernel_mma<<<EBLOCKS, 256, EDGE_SMEM>>>(
            cur, l, ei, eattr,
            mW1 + (size_t)l * 384 * 128, mb1 + (size_t)l * 128,
            aW2 + (size_t)l * 256, ab2 + (size_t)l * 1);
        node_hidden_kernel<<<dim3(NBLOCKS, 2), 256, NODE_SMEM>>>(
            cur, l, nW1 + (size_t)l * 256 * 256, nb1 + (size_t)l * 256);
        node_out_kernel<<<NBLOCKS, 256, NODE_SMEM>>>(
            cur, nxt, nW2 + (size_t)l * 256 * 128, nb2 + (size_t)l * 128,
            (l == 2) ? (float*)d_out : nullptr);
    }
}

// round 16
// speedup vs baseline: 1.2594x; 1.2594x over previous
#include <cuda_runtime.h>
#include <cuda_bf16.h>
#include <cstdint>
#include <cstddef>

#define NNODES 50000
#define NEDGES 500000
#define HDIM   128
#define EBLOCKS ((NEDGES + 127) / 128)
#define NBLOCKS ((NNODES + 127) / 128)

typedef unsigned long long ull;

// ---------------- device scratch ----------------
__device__ float g_x[2][(size_t)NNODES * HDIM];
__device__ float g_pos[2][(size_t)NNODES * 3];
__device__ float g_intra[(size_t)NNODES * HDIM];   // hsum = sum_e h_e per dst
__device__ float g_pdelta[(size_t)NNODES * 3];
__device__ float g_hidden[(size_t)NNODES * 256];
__device__ float g_P[(size_t)NNODES * HDIM];
__device__ float g_Q[(size_t)NNODES * HDIM];
__device__ float g_C1[3][128 * 256];   // W2 @ aW1
__device__ float g_C2[3][128 * 256];   // W2 @ nW1[128:]
__device__ float g_c1b[3][256];        // b2 @ aW1 + ab1
__device__ float g_c2b[3][256];        // b2 @ nW1[128:]
// per-block pre-swizzled bf16 h tiles (128x128 each)
__device__ unsigned short g_hbf[(size_t)EBLOCKS * 128 * 128];
__device__ int   g_deg[NNODES];
__device__ int   g_idx64;

__device__ __forceinline__ void red_add_v4(float* a, float x, float y, float z, float w) {
    asm volatile("red.global.add.v4.f32 [%0], {%1,%2,%3,%4};"
                 :: "l"(a), "f"(x), "f"(y), "f"(z), "f"(w) : "memory");
}
__device__ __forceinline__ void red_add_f32(float* a, float v) {
    asm volatile("red.global.add.f32 [%0], %1;" :: "l"(a), "f"(v) : "memory");
}
__device__ __forceinline__ uint32_t smem_to_u32(const void* p) {
    uint32_t a;
    asm("{ .reg .u64 t; cvta.to.shared.u64 t, %1; cvt.u32.u64 %0, t; }" : "=r"(a) : "l"(p));
    return a;
}

// ---------------- packed fp32x2 ----------------
__device__ __forceinline__ ull pk2(float lo, float hi) {
    ull r; asm("mov.b64 %0, {%1, %2};" : "=l"(r) : "f"(lo), "f"(hi)); return r;
}
__device__ __forceinline__ void upk2(float& lo, float& hi, ull v) {
    asm("mov.b64 {%0, %1}, %2;" : "=f"(lo), "=f"(hi) : "l"(v));
}
__device__ __forceinline__ void fmax2(ull& c, ull a, ull b) {
    asm("fma.rn.f32x2 %0, %1, %2, %0;" : "+l"(c) : "l"(a), "l"(b));
}

// ---------------- mma.sync helpers (fragment mapping verified R9/R14) ----------
__device__ __forceinline__ void ldsm_x4(uint32_t addr, uint32_t* r) {
    asm volatile("ldmatrix.sync.aligned.m8n8.x4.shared.b16 {%0,%1,%2,%3}, [%4];"
                 : "=r"(r[0]), "=r"(r[1]), "=r"(r[2]), "=r"(r[3]) : "r"(addr));
}
__device__ __forceinline__ void mma_bf16(float* c, const uint32_t* a, const uint32_t* b) {
    asm volatile("mma.sync.aligned.m16n8k16.row.col.f32.bf16.bf16.f32 "
                 "{%0,%1,%2,%3}, {%4,%5,%6,%7}, {%8,%9}, {%0,%1,%2,%3};"
                 : "+f"(c[0]), "+f"(c[1]), "+f"(c[2]), "+f"(c[3])
                 : "r"(a[0]), "r"(a[1]), "r"(a[2]), "r"(a[3]), "r"(b[0]), "r"(b[1]));
}

// SW128-swizzled byte offset in a 128x128 bf16 tile (validated R9)
__device__ __forceinline__ uint32_t sw_off(int r, int c) {
    uint32_t b = ((uint32_t)(c >> 6) << 14) + ((uint32_t)(r >> 3) << 10) +
                 ((uint32_t)(r & 7) << 7) + ((uint32_t)(c & 63) << 1);
    return b ^ ((b >> 3) & 0x70);
}

// warp 16x128 slice, SINGLE-term bf16 (acc-MLP only; error budget analysis in log)
__device__ __forceinline__ void warp_mma1(
    float (*acc)[4], uint32_t a_u, uint32_t w_u, int row0, int lane)
{
    const int arow  = row0 + (lane & 15);
    const int acolh = (lane >> 4) * 8;
    const int btile = lane >> 3;
    const int brow  = lane & 7;
    const int bnt   = (btile >> 1) * 8;
    const int bkh   = (btile & 1) * 8;
    for (int k0 = 0; k0 < 8; k0++) {
        uint32_t ah[4];
        ldsm_x4(a_u + sw_off(arow, k0 * 16 + acolh), ah);
        uint32_t bh[32];
#pragma unroll
        for (int p = 0; p < 8; p++)
            ldsm_x4(w_u + sw_off(p * 16 + bnt + brow, k0 * 16 + bkh), &bh[p * 4]);
#pragma unroll
        for (int nt = 0; nt < 16; nt++) mma_bf16(acc[nt], ah, &bh[nt * 2]);
    }
}

// ---------------- SIMT GEMM helpers ----------------
__device__ __forceinline__ void load_w128(float* Ws, const float* __restrict__ src, int row_stride)
{
    for (int idx = threadIdx.x; idx < 128 * 32; idx += 256) {
        int r = idx >> 5, c4 = idx & 31;
        reinterpret_cast<float4*>(Ws + r * 128)[c4] =
            reinterpret_cast<const float4*>(src + (size_t)r * row_stride)[c4];
    }
}
__device__ __forceinline__ void mm128p(const float* __restrict__ As, const float* __restrict__ Ws,
                                       int rb, int c0, ull (*acc)[4])
{
#pragma unroll 4
    for (int k = 0; k < 128; k++) {
        ull av[8];
#pragma unroll
        for (int i = 0; i < 8; i++) { float a = As[(rb + i) * 129 + k]; av[i] = pk2(a, a); }
        const ull* w0 = reinterpret_cast<const ull*>(Ws + k * 128 + c0);
        const ull* w1 = reinterpret_cast<const ull*>(Ws + k * 128 + c0 + 64);
        const ull b0 = w0[0], b1 = w0[1], b2 = w1[0], b3 = w1[1];
#pragma unroll
        for (int i = 0; i < 8; i++) {
            fmax2(acc[i][0], av[i], b0);
            fmax2(acc[i][1], av[i], b1);
            fmax2(acc[i][2], av[i], b2);
            fmax2(acc[i][3], av[i], b3);
        }
    }
}

#define EDGE_SMEM ((128 * 129 + 128 * 128) * 4 + 2 * 128 * 4)
#define ACC_SMEM  (1024 + 32768 + 32768)
#define NODE_SMEM ((128 * 129 + 128 * 128) * 4)

#define DECL_SMEM_RAW extern __shared__ __align__(1024) char sm_raw[]

// ---------------- prep / deg ----------------
__global__ void prep_kernel(const float* __restrict__ x, const float* __restrict__ pos,
                            const void* __restrict__ ei)
{
    const long long stride = (long long)gridDim.x * blockDim.x;
    const long long t0 = (long long)blockIdx.x * blockDim.x + threadIdx.x;
    float4* xb = reinterpret_cast<float4*>(g_x[0]);
    const float4* xs = reinterpret_cast<const float4*>(x);
    float4* ib = reinterpret_cast<float4*>(g_intra);
    const float4 z4 = make_float4(0.f, 0.f, 0.f, 0.f);
    const long long nx4 = (long long)NNODES * (HDIM / 4);
    for (long long t = t0; t < nx4; t += stride) { xb[t] = xs[t]; ib[t] = z4; }
    for (long long t = t0; t < (long long)NNODES * 3; t += stride) {
        g_pos[0][t] = pos[t]; g_pdelta[t] = 0.f;
    }
    for (long long t = t0; t < NNODES; t += stride) g_deg[t] = 0;
    if (t0 == 0) {
        const unsigned* u = (const unsigned*)ei;
        int is64 = 1;
        for (int k = 0; k < 128; k++) if (u[2 * k + 1] != 0u) { is64 = 0; break; }
        g_idx64 = is64;
    }
}

__global__ void deg_kernel(const void* __restrict__ ei)
{
    int e = blockIdx.x * blockDim.x + threadIdx.x;
    if (e >= NEDGES) return;
    int d;
    if (g_idx64) d = (int)((const long long*)ei)[(size_t)NEDGES + e];
    else         d = ((const int*)ei)[NEDGES + e];
    atomicAdd(&g_deg[d], 1);
}

// ---------------- fold kernels ----------------
__global__ void __launch_bounds__(256) fold_mat_kernel(
    const float* __restrict__ mW2, const float* __restrict__ aW1,
    const float* __restrict__ nW1)
{
    DECL_SMEM_RAW;
    float* smf = reinterpret_cast<float*>(sm_raw);
    float* As = smf;
    float* Ws = smf + 128 * 129;

    const int tid  = threadIdx.x;
    const int rb   = (tid >> 4) * 8;
    const int c0   = (tid & 15) * 4;
    const int half = blockIdx.x;
    const int l    = blockIdx.y;
    const int tgt  = blockIdx.z;

    const float* A = mW2 + (size_t)l * 128 * 128;
    const float* W = tgt == 0 ? (aW1 + (size_t)l * 128 * 256 + half * 128)
                              : (nW1 + (size_t)l * 256 * 256 + (size_t)128 * 256 + half * 128);
    float* out = (tgt == 0 ? g_C1[l] : g_C2[l]) + half * 128;

    for (int idx = tid; idx < 128 * 32; idx += 256) {
        int r = idx >> 5, c4 = idx & 31;
        float4 v = reinterpret_cast<const float4*>(A + (size_t)r * 128)[c4];
        float* a = As + r * 129 + c4 * 4;
        a[0] = v.x; a[1] = v.y; a[2] = v.z; a[3] = v.w;
    }
    load_w128(Ws, W, 256);
    __syncthreads();

    ull acc[8][4];
#pragma unroll
    for (int i = 0; i < 8; i++)
#pragma unroll
        for (int j = 0; j < 4; j++) acc[i][j] = 0ull;
    mm128p(As, Ws, rb, c0, acc);

#pragma unroll
    for (int i = 0; i < 8; i++) {
        float* orow = out + (size_t)(rb + i) * 256;
        float v0, v1;
        upk2(v0, v1, acc[i][0]); orow[c0] = v0;      orow[c0 + 1] = v1;
        upk2(v0, v1, acc[i][1]); orow[c0 + 2] = v0;  orow[c0 + 3] = v1;
        upk2(v0, v1, acc[i][2]); orow[c0 + 64] = v0; orow[c0 + 65] = v1;
        upk2(v0, v1, acc[i][3]); orow[c0 + 66] = v0; orow[c0 + 67] = v1;
    }
}

__global__ void fold_bias_kernel(
    const float* __restrict__ mb2, const float* __restrict__ aW1,
    const float* __restrict__ ab1, const float* __restrict__ nW1)
{
    const int c = threadIdx.x;
    const int l = blockIdx.x;
    const float* b2 = mb2 + (size_t)l * 128;
    float s1 = 0.f, s2 = 0.f;
    const float* A1 = aW1 + (size_t)l * 128 * 256;
    const float* A2 = nW1 + (size_t)l * 256 * 256 + (size_t)128 * 256;
    for (int j = 0; j < 128; j++) {
        float b = b2[j];
        s1 += b * A1[(size_t)j * 256 + c];
        s2 += b * A2[(size_t)j * 256 + c];
    }
    g_c1b[l][c] = s1 + ab1[(size_t)l * 256 + c];
    g_c2b[l][c] = s2;
}

// ---------------- pq kernel ----------------
__global__ void __launch_bounds__(256) pq_kernel(int cur, const float* __restrict__ mW1)
{
    DECL_SMEM_RAW;
    float* smf = reinterpret_cast<float*>(sm_raw);
    float* As = smf;
    float* Ws = smf + 128 * 129;

    const float* __restrict__ x = g_x[cur];
    const int tid = threadIdx.x;
    const int rb  = (tid >> 4) * 8;
    const int c0  = (tid & 15) * 4;
    const int n0  = blockIdx.x * 128;
    const int half = blockIdx.y;

    for (int idx = tid; idx < 128 * 32; idx += 256) {
        int r = idx >> 5, c4 = idx & 31;
        int n = n0 + r; if (n > NNODES - 1) n = NNODES - 1;
        float4 v = reinterpret_cast<const float4*>(x + (size_t)n * HDIM)[c4];
        float* a = As + r * 129 + c4 * 4;
        a[0] = v.x; a[1] = v.y; a[2] = v.z; a[3] = v.w;
    }
    load_w128(Ws, mW1 + (size_t)half * 128 * HDIM, HDIM);
    __syncthreads();

    ull acc[8][4];
#pragma unroll
    for (int i = 0; i < 8; i++)
#pragma unroll
        for (int j = 0; j < 4; j++) acc[i][j] = 0ull;
    mm128p(As, Ws, rb, c0, acc);

    float* __restrict__ out = half ? g_Q : g_P;
#pragma unroll
    for (int i = 0; i < 8; i++) {
        int n = n0 + rb + i;
        if (n >= NNODES) break;
        float* orow = out + (size_t)n * HDIM;
        float v0, v1;
        upk2(v0, v1, acc[i][0]); orow[c0] = v0;     orow[c0 + 1] = v1;
        upk2(v0, v1, acc[i][1]); orow[c0 + 2] = v0; orow[c0 + 3] = v1;
        upk2(v0, v1, acc[i][2]); orow[c0 + 64] = v0; orow[c0 + 65] = v1;
        upk2(v0, v1, acc[i][3]); orow[c0 + 66] = v0; orow[c0 + 67] = v1;
    }
}

// ---------------- edge GEMM1 (fp32 exact): h -> intra + g_hbf ----------------
__global__ void __launch_bounds__(256) edge_gemm1_kernel(
    int cur, const void* __restrict__ ei, const float* __restrict__ eattr,
    const float* __restrict__ mW1, const float* __restrict__ mb1)
{
    DECL_SMEM_RAW;
    float* smf = reinterpret_cast<float*>(sm_raw);
    float* As = smf;
    float* Ws = smf + 128 * 129;
    int* sdst = (int*)(smf + 128 * 129 + 128 * 128);
    int* ssrc = sdst + 128;

    const int tid = threadIdx.x;
    const int rb  = (tid >> 4) * 8;
    const int c0  = (tid & 15) * 4;
    const int e0  = blockIdx.x * 128;

    if (tid < 128) {
        int e = e0 + tid; if (e > NEDGES - 1) e = NEDGES - 1;
        int s, d;
        if (g_idx64) { const long long* p = (const long long*)ei;
                       s = (int)p[e]; d = (int)p[(size_t)NEDGES + e]; }
        else         { const int* p = (const int*)ei; s = p[e]; d = p[NEDGES + e]; }
        ssrc[tid] = s; sdst[tid] = d;
    }
    for (int idx = tid; idx < 128 * 32; idx += 256) {
        int r = idx >> 5, c4 = idx & 31;
        int e = e0 + r; if (e > NEDGES - 1) e = NEDGES - 1;
        float4 v = reinterpret_cast<const float4*>(eattr + (size_t)e * HDIM)[c4];
        float* a = As + r * 129 + c4 * 4;
        a[0] = v.x; a[1] = v.y; a[2] = v.z; a[3] = v.w;
    }
    load_w128(Ws, mW1 + (size_t)2 * 128 * HDIM, HDIM);
    __syncthreads();

    float bv[8];
#pragma unroll
    for (int q = 0; q < 2; q++)
#pragma unroll
        for (int j = 0; j < 4; j++) bv[q * 4 + j] = __ldg(mb1 + c0 + q * 64 + j);

    ull acc[8][4];
#pragma unroll
    for (int i = 0; i < 8; i++) {
        int r = rb + i;
        const int d = sdst[r], s = ssrc[r];
        const float4 p0 = *reinterpret_cast<const float4*>(g_P + (size_t)d * HDIM + c0);
        const float4 p1 = *reinterpret_cast<const float4*>(g_P + (size_t)d * HDIM + c0 + 64);
        const float4 q0 = *reinterpret_cast<const float4*>(g_Q + (size_t)s * HDIM + c0);
        const float4 q1 = *reinterpret_cast<const float4*>(g_Q + (size_t)s * HDIM + c0 + 64);
        acc[i][0] = pk2(bv[0] + p0.x + q0.x, bv[1] + p0.y + q0.y);
        acc[i][1] = pk2(bv[2] + p0.z + q0.z, bv[3] + p0.w + q0.w);
        acc[i][2] = pk2(bv[4] + p1.x + q1.x, bv[5] + p1.y + q1.y);
        acc[i][3] = pk2(bv[6] + p1.z + q1.z, bv[7] + p1.w + q1.w);
    }
    mm128p(As, Ws, rb, c0, acc);

    // relu -> h; intra seg-sum; bf16 h -> g_hbf (pre-swizzled tile)
    unsigned short* tile = g_hbf + (size_t)blockIdx.x * 128 * 128;
    float h[8][8];
#pragma unroll
    for (int i = 0; i < 8; i++) {
        upk2(h[i][0], h[i][1], acc[i][0]);
        upk2(h[i][2], h[i][3], acc[i][1]);
        upk2(h[i][4], h[i][5], acc[i][2]);
        upk2(h[i][6], h[i][7], acc[i][3]);
#pragma unroll
        for (int jj = 0; jj < 8; jj++) h[i][jj] = fmaxf(h[i][jj], 0.f);
        int r = rb + i;
#pragma unroll
        for (int q = 0; q < 2; q++) {
            int c = c0 + q * 64;
            uint32_t v01 = (uint32_t)__bfloat16_as_ushort(__float2bfloat16_rn(h[i][q * 4 + 0])) |
                           ((uint32_t)__bfloat16_as_ushort(__float2bfloat16_rn(h[i][q * 4 + 1])) << 16);
            uint32_t v23 = (uint32_t)__bfloat16_as_ushort(__float2bfloat16_rn(h[i][q * 4 + 2])) |
                           ((uint32_t)__bfloat16_as_ushort(__float2bfloat16_rn(h[i][q * 4 + 3])) << 16);
            *(uint32_t*)((char*)tile + sw_off(r, c))     = v01;
            *(uint32_t*)((char*)tile + sw_off(r, c + 2)) = v23;
        }
    }
#pragma unroll
    for (int i = 0; i < 8; i++) {
        int r = rb + i;
        if (e0 + r < NEDGES) {
            float* base = g_intra + (size_t)sdst[r] * HDIM + c0;
            red_add_v4(base,      h[i][0], h[i][1], h[i][2], h[i][3]);
            red_add_v4(base + 64, h[i][4], h[i][5], h[i][6], h[i][7]);
        }
    }
}

// ---------------- edge acc (bf16 1-term mma, 2 CTAs/SM) ----------------
__global__ void __launch_bounds__(256, 2) edge_acc_kernel(
    int cur, int layer, const void* __restrict__ ei,
    const float* __restrict__ aW2, const float* __restrict__ ab2)
{
    DECL_SMEM_RAW;
    char* sm = sm_raw;
    int* sdst = (int*)sm;                 // [128]
    int* ssrc = sdst + 128;               // [128]
    char* A_bf = sm + 1024;               // 32 KB
    char* W_bf = sm + 1024 + 32768;       // 32 KB
    const uint32_t a_u = smem_to_u32(A_bf);
    const uint32_t w_u = smem_to_u32(W_bf);

    const float* __restrict__ C1  = g_C1[layer];
    const float* __restrict__ c1b = g_c1b[layer];
    const float* __restrict__ pos = g_pos[cur];

    const int tid  = threadIdx.x;
    const int lane = tid & 31;
    const int wid  = tid >> 5;
    const int row0 = wid * 16;
    const int e0   = blockIdx.x * 128;

    if (tid < 128) {
        int e = e0 + tid; if (e > NEDGES - 1) e = NEDGES - 1;
        int s, d;
        if (g_idx64) { const long long* p = (const long long*)ei;
                       s = (int)p[e]; d = (int)p[(size_t)NEDGES + e]; }
        else         { const int* p = (const int*)ei; s = p[e]; d = p[NEDGES + e]; }
        ssrc[tid] = s; sdst[tid] = d;
    }
    // stage pre-swizzled h tile: pure float4 copy
    {
        const float4* src = reinterpret_cast<const float4*>(g_hbf + (size_t)blockIdx.x * 128 * 128);
        float4* dst = reinterpret_cast<float4*>(A_bf);
        for (int i = tid; i < 2048; i += 256) dst[i] = src[i];
    }
    // stage C1^T half0 as bf16: tile[n][k] = C1[k][n]
    for (int idx = tid; idx < 128 * 32; idx += 256) {
        int k = idx >> 5, n0 = (idx & 31) * 4;
        float4 v = *reinterpret_cast<const float4*>(C1 + (size_t)k * 256 + n0);
        *(unsigned short*)(W_bf + sw_off(n0 + 0, k)) = __bfloat16_as_ushort(__float2bfloat16_rn(v.x));
        *(unsigned short*)(W_bf + sw_off(n0 + 1, k)) = __bfloat16_as_ushort(__float2bfloat16_rn(v.y));
        *(unsigned short*)(W_bf + sw_off(n0 + 2, k)) = __bfloat16_as_ushort(__float2bfloat16_rn(v.z));
        *(unsigned short*)(W_bf + sw_off(n0 + 3, k)) = __bfloat16_as_ushort(__float2bfloat16_rn(v.w));
    }
    __syncthreads();

    const int lr0 = row0 + (lane >> 2);
    const int lr1 = lr0 + 8;
    const int cb  = 2 * (lane & 3);

    float acc[16][4];
    float wacc0 = 0.f, wacc1 = 0.f;
    for (int hp = 0; hp < 2; hp++) {
#pragma unroll
        for (int nt = 0; nt < 16; nt++) {
            float2 b = *reinterpret_cast<const float2*>(c1b + hp * 128 + nt * 8 + cb);
            acc[nt][0] = b.x; acc[nt][1] = b.y; acc[nt][2] = b.x; acc[nt][3] = b.y;
        }
        warp_mma1(acc, a_u, w_u, row0, lane);
#pragma unroll
        for (int nt = 0; nt < 16; nt++) {
            int c = hp * 128 + nt * 8 + cb;
            float2 wv = *reinterpret_cast<const float2*>(aW2 + c);
            wacc0 += fmaxf(acc[nt][0], 0.f) * wv.x + fmaxf(acc[nt][1], 0.f) * wv.y;
            wacc1 += fmaxf(acc[nt][2], 0.f) * wv.x + fmaxf(acc[nt][3], 0.f) * wv.y;
        }
        if (hp == 0) {
            __syncthreads();
            for (int idx = tid; idx < 128 * 32; idx += 256) {
                int k = idx >> 5, n0 = (idx & 31) * 4;
                float4 v = *reinterpret_cast<const float4*>(C1 + (size_t)k * 256 + 128 + n0);
                *(unsigned short*)(W_bf + sw_off(n0 + 0, k)) = __bfloat16_as_ushort(__float2bfloat16_rn(v.x));
                *(unsigned short*)(W_bf + sw_off(n0 + 1, k)) = __bfloat16_as_ushort(__float2bfloat16_rn(v.y));
                *(unsigned short*)(W_bf + sw_off(n0 + 2, k)) = __bfloat16_as_ushort(__float2bfloat16_rn(v.z));
                *(unsigned short*)(W_bf + sw_off(n0 + 3, k)) = __bfloat16_as_ushort(__float2bfloat16_rn(v.w));
            }
            __syncthreads();
        }
    }
    wacc0 += __shfl_xor_sync(0xffffffffu, wacc0, 1);
    wacc0 += __shfl_xor_sync(0xffffffffu, wacc0, 2);
    wacc1 += __shfl_xor_sync(0xffffffffu, wacc1, 1);
    wacc1 += __shfl_xor_sync(0xffffffffu, wacc1, 2);

    if ((lane & 3) == 0) {
        const float b2 = __ldg(ab2);
        int rr[2] = {lr0, lr1};
        float wa[2] = {wacc0, wacc1};
#pragma unroll
        for (int i = 0; i < 2; i++) {
            int r = rr[i];
            if (e0 + r >= NEDGES) continue;
            int s = ssrc[r], d = sdst[r];
            float rx = pos[(size_t)s * 3 + 0] - pos[(size_t)d * 3 + 0];
            float ry = pos[(size_t)s * 3 + 1] - pos[(size_t)d * 3 + 1];
            float rz = pos[(size_t)s * 3 + 2] - pos[(size_t)d * 3 + 2];
            float inv = rsqrtf(rx * rx + ry * ry + rz * rz);
            float w = (wa[i] + b2) * inv;
            float* pb = g_pdelta + (size_t)d * 3;
            red_add_f32(pb + 0, w * rx);
            red_add_f32(pb + 1, w * ry);
            red_add_f32(pb + 2, w * rz);
        }
    }
}

// ---------------- node hidden ----------------
__global__ void __launch_bounds__(256) node_hidden_kernel(
    int cur, int layer, const float* __restrict__ nW1a, const float* __restrict__ nb1)
{
    DECL_SMEM_RAW;
    float* smf = reinterpret_cast<float*>(sm_raw);
    float* As = smf;
    float* Ws = smf + 128 * 129;

    const float* __restrict__ C2  = g_C2[layer];
    const float* __restrict__ c2b = g_c2b[layer];

    const float* __restrict__ x = g_x[cur];
    const int tid = threadIdx.x;
    const int rb  = (tid >> 4) * 8;
    const int c0  = (tid & 15) * 4;
    const int n0  = blockIdx.x * 128;
    const int hp  = blockIdx.y;

    ull acc[8][4];
#pragma unroll
    for (int i = 0; i < 8; i++) {
        const float* bb = nb1 + hp * 128;
        acc[i][0] = pk2(bb[c0], bb[c0 + 1]);
        acc[i][1] = pk2(bb[c0 + 2], bb[c0 + 3]);
        acc[i][2] = pk2(bb[c0 + 64], bb[c0 + 65]);
        acc[i][3] = pk2(bb[c0 + 66], bb[c0 + 67]);
    }

    for (int kc = 0; kc < 2; kc++) {
        for (int idx = tid; idx < 128 * 32; idx += 256) {
            int r = idx >> 5, c4 = idx & 31;
            int n = n0 + r; if (n > NNODES - 1) n = NNODES - 1;
            float4 v;
            if (kc == 0) v = reinterpret_cast<const float4*>(x + (size_t)n * HDIM)[c4];
            else {
                v = reinterpret_cast<const float4*>(g_intra + (size_t)n * HDIM)[c4];
                float dn = 1.f / fmaxf((float)g_deg[n], 1.f);
                v.x *= dn; v.y *= dn; v.z *= dn; v.w *= dn;
            }
            float* a = As + r * 129 + c4 * 4;
            a[0] = v.x; a[1] = v.y; a[2] = v.z; a[3] = v.w;
        }
        if (kc == 0) load_w128(Ws, nW1a + hp * 128, 256);
        else         load_w128(Ws, C2 + hp * 128, 256);
        __syncthreads();
        mm128p(As, Ws, rb, c0, acc);
        __syncthreads();
    }

#pragma unroll
    for (int i = 0; i < 8; i++) {
        int n = n0 + rb + i;
        if (n >= NNODES) break;
        float kap = g_deg[n] > 0 ? 1.f : 0.f;
        const float* cb = c2b + hp * 128;
        float* hrow = g_hidden + (size_t)n * 256 + hp * 128;
        float v0, v1;
        upk2(v0, v1, acc[i][0]);
        hrow[c0] = fmaxf(v0 + kap * cb[c0], 0.f);         hrow[c0 + 1] = fmaxf(v1 + kap * cb[c0 + 1], 0.f);
        upk2(v0, v1, acc[i][1]);
        hrow[c0 + 2] = fmaxf(v0 + kap * cb[c0 + 2], 0.f); hrow[c0 + 3] = fmaxf(v1 + kap * cb[c0 + 3], 0.f);
        upk2(v0, v1, acc[i][2]);
        hrow[c0 + 64] = fmaxf(v0 + kap * cb[c0 + 64], 0.f); hrow[c0 + 65] = fmaxf(v1 + kap * cb[c0 + 65], 0.f);
        upk2(v0, v1, acc[i][3]);
        hrow[c0 + 66] = fmaxf(v0 + kap * cb[c0 + 66], 0.f); hrow[c0 + 67] = fmaxf(v1 + kap * cb[c0 + 67], 0.f);
    }
}

// ---------------- node out ----------------
__global__ void __launch_bounds__(256) node_out_kernel(
    int cur, int nxt, const float* __restrict__ nW2, const float* __restrict__ nb2,
    float* __restrict__ pout)
{
    DECL_SMEM_RAW;
    float* smf = reinterpret_cast<float*>(sm_raw);
    float* As = smf;
    float* Ws = smf + 128 * 129;

    const int tid = threadIdx.x;
    const int rb  = (tid >> 4) * 8;
    const int c0  = (tid & 15) * 4;
    const int n0  = blockIdx.x * 128;

    ull acc[8][4];
#pragma unroll
    for (int i = 0; i < 8; i++) {
        acc[i][0] = pk2(nb2[c0], nb2[c0 + 1]);
        acc[i][1] = pk2(nb2[c0 + 2], nb2[c0 + 3]);
        acc[i][2] = pk2(nb2[c0 + 64], nb2[c0 + 65]);
        acc[i][3] = pk2(nb2[c0 + 66], nb2[c0 + 67]);
    }

    for (int kc = 0; kc < 2; kc++) {
        for (int idx = tid; idx < 128 * 32; idx += 256) {
            int r = idx >> 5, c4 = idx & 31;
            int n = n0 + r; if (n > NNODES - 1) n = NNODES - 1;
            float4 v = reinterpret_cast<const float4*>(g_hidden + (size_t)n * 256 + kc * 128)[c4];
            float* a = As + r * 129 + c4 * 4;
            a[0] = v.x; a[1] = v.y; a[2] = v.z; a[3] = v.w;
        }
        load_w128(Ws, nW2 + (size_t)kc * 128 * 128, 128);
        __syncthreads();
        mm128p(As, Ws, rb, c0, acc);
        __syncthreads();
    }

    float* __restrict__ xo = g_x[nxt];
#pragma unroll
    for (int i = 0; i < 8; i++) {
        int n = n0 + rb + i;
        if (n >= NNODES) break;
        float* xrow = xo + (size_t)n * HDIM;
        float v0, v1;
        upk2(v0, v1, acc[i][0]); xrow[c0] = v0;     xrow[c0 + 1] = v1;
        upk2(v0, v1, acc[i][1]); xrow[c0 + 2] = v0; xrow[c0 + 3] = v1;
        upk2(v0, v1, acc[i][2]); xrow[c0 + 64] = v0; xrow[c0 + 65] = v1;
        upk2(v0, v1, acc[i][3]); xrow[c0 + 66] = v0; xrow[c0 + 67] = v1;
    }

    for (int idx = tid; idx < 128 * 3; idx += 256) {
        int r = idx / 3, c = idx % 3;
        int n = n0 + r;
        if (n < NNODES) {
            float dn = 1.f / fmaxf((float)g_deg[n], 1.f);
            float p = g_pos[cur][(size_t)n * 3 + c] + g_pdelta[(size_t)n * 3 + c] * dn;
            g_pos[nxt][(size_t)n * 3 + c] = p;
            if (pout) pout[(size_t)n * 3 + c] = p;
            g_pdelta[(size_t)n * 3 + c] = 0.f;
        }
    }
    const float4 z4 = make_float4(0.f, 0.f, 0.f, 0.f);
    for (int idx = tid; idx < 128 * 32; idx += 256) {
        int r = idx >> 5, c4 = idx & 31;
        int n = n0 + r;
        if (n < NNODES)
            reinterpret_cast<float4*>(g_intra + (size_t)n * HDIM)[c4] = z4;
    }
}

extern "C" void kernel_launch(void* const* d_in, const int* in_sizes, int n_in,
                              void* d_out, int out_size)
{
    const float* x     = (const float*)d_in[0];
    const void*  ei    = d_in[1];
    const float* eattr = (const float*)d_in[2];
    const float* pos   = (const float*)d_in[3];
    const float* mW1 = (const float*)d_in[4];
    const float* mb1 = (const float*)d_in[5];
    const float* mW2 = (const float*)d_in[6];
    const float* mb2 = (const float*)d_in[7];
    const float* aW1 = (const float*)d_in[8];
    const float* ab1 = (const float*)d_in[9];
    const float* aW2 = (const float*)d_in[10];
    const float* ab2 = (const float*)d_in[11];
    const float* nW1 = (const float*)d_in[12];
    const float* nb1 = (const float*)d_in[13];
    const float* nW2 = (const float*)d_in[14];
    const float* nb2 = (const float*)d_in[15];

    cudaFuncSetAttribute(edge_gemm1_kernel, cudaFuncAttributeMaxDynamicSharedMemorySize, EDGE_SMEM);
    cudaFuncSetAttribute(edge_acc_kernel, cudaFuncAttributeMaxDynamicSharedMemorySize, ACC_SMEM);
    cudaFuncSetAttribute(pq_kernel, cudaFuncAttributeMaxDynamicSharedMemorySize, NODE_SMEM);
    cudaFuncSetAttribute(fold_mat_kernel, cudaFuncAttributeMaxDynamicSharedMemorySize, NODE_SMEM);
    cudaFuncSetAttribute(node_hidden_kernel, cudaFuncAttributeMaxDynamicSharedMemorySize, NODE_SMEM);
    cudaFuncSetAttribute(node_out_kernel, cudaFuncAttributeMaxDynamicSharedMemorySize, NODE_SMEM);

    prep_kernel<<<1024, 256>>>(x, pos, ei);
    deg_kernel<<<(NEDGES + 255) / 256, 256>>>(ei);
    fold_mat_kernel<<<dim3(2, 3, 2), 256, NODE_SMEM>>>(mW2, aW1, nW1);
    fold_bias_kernel<<<3, 256>>>(mb2, aW1, ab1, nW1);

    for (int l = 0; l < 3; l++) {
        int cur = l & 1, nxt = cur ^ 1;
        pq_kernel<<<dim3(NBLOCKS, 2), 256, NODE_SMEM>>>(cur, mW1 + (size_t)l * 384 * 128);
        edge_gemm1_kernel<<<EBLOCKS, 256, EDGE_SMEM>>>(
            cur, ei, eattr, mW1 + (size_t)l * 384 * 128, mb1 + (size_t)l * 128);
        edge_acc_kernel<<<EBLOCKS, 256, ACC_SMEM>>>(
            cur, l, ei, aW2 + (size_t)l * 256, ab2 + (size_t)l * 1);
        node_hidden_kernel<<<dim3(NBLOCKS, 2), 256, NODE_SMEM>>>(
            cur, l, nW1 + (size_t)l * 256 * 256, nb1 + (size_t)l * 256);
        node_out_kernel<<<NBLOCKS, 256, NODE_SMEM>>>(
            cur, nxt, nW2 + (size_t)l * 256 * 128, nb2 + (size_t)l * 128,
            (l == 2) ? (float*)d_out : nullptr);
    }
}